// round 13
// baseline (speedup 1.0000x reference)
#include <cuda_runtime.h>
#include <cuda_fp16.h>
#include <mma.h>
#include <math.h>
#include <cstdint>

using namespace nvcuda;

// ---------------- problem constants ----------------
#define BB    64
#define PP    196
#define ENC   512
#define EE    1024
#define HH    1024
#define AA    512
#define VV    20000
#define LL    25
#define TT    24

// ---------------- scratch layout (float units; half regions cast) ----------------
#define OFF_ATT_ENC  0u            // half 12544*512
#define OFF_EBIAS    6422528u      // fp32 1536*4096
#define OFF_WCTX     12713984u     // half 512*4096  (W_ih rows 1024.., col-permuted)
#define OFF_WIH      13762560u     // half 1024*4096 (col-permuted)
#define OFF_WCOMB    15859712u     // half 1024*5120 ([Wcat | Whh_perm])
#define OFF_BCAT     18481152u     // fp32 1024
#define OFF_BREC     18482176u     // fp32 4096
#define OFF_MEAN     18486272u     // half 64*512
#define OFF_SX       18502656u     // half 2*64*1536 ([gc|h])
#define OFF_C        18600960u     // fp32 64*1024
#define OFF_COMB     18666496u     // fp32 64*5120 (attdec | fbeta | hpart)
#define OFF_HALL     18994176u     // half 1536*1024
#define OFF_ENC_H    19780608u     // half 12544*512
#define OFF_EMBG     22991872u     // half 1536*1024
#define OFF_WFC_H    23778304u     // half 1024*20000
#define OFF_WEA_H    34018304u     // half 512*512
#define OFF_W0       34149376u     // half 512*2048
#define OFF_B0       34673664u     // fp32 2048
#define SCRATCH_TOTAL 34675712u

__device__ __align__(256) float g_scratch[SCRATCH_TOTAL];

// monotonic counting barriers (reset by prep_kernel each launch)
__device__ unsigned g_c_attdec = 0;
__device__ unsigned g_c_pre    = 0;
__device__ unsigned g_c_step   = 0;

__device__ __forceinline__ void cp16(unsigned int dst, const void* src, int pred)
{
    asm volatile(
        "{\n\t.reg .pred p;\n\t"
        "setp.ne.b32 p, %2, 0;\n\t"
        "@p cp.async.cg.shared.global [%0], [%1], 16;\n\t}\n"
        :: "r"(dst), "l"(src), "r"(pred));
}

__device__ __forceinline__ void bar_arrive(unsigned* c)
{
    __syncthreads();
    if (threadIdx.x == 0) { __threadfence(); atomicAdd(c, 1u); }
}
__device__ __forceinline__ void bar_wait(unsigned* c, unsigned target)
{
    if (threadIdx.x == 0) {
        while (*(volatile unsigned*)c < target) {}
        __threadfence();
    }
    __syncthreads();
}

// ---------------- prep ----------------
__global__ void prep_kernel(const float* __restrict__ Wdec, const float* __restrict__ Wfb,
                            const float* __restrict__ bdec, const float* __restrict__ bfb,
                            const float* __restrict__ Wih,  const float* __restrict__ Whh,
                            const float* __restrict__ bih,  const float* __restrict__ bhh,
                            const float* __restrict__ enc,  const float* __restrict__ emb,
                            const float* __restrict__ Wfc,  const float* __restrict__ Wea,
                            const float* __restrict__ Wih0, const float* __restrict__ Wic0,
                            const float* __restrict__ bih0, const float* __restrict__ bic0,
                            const int*   __restrict__ caps)
{
    __half* Wctx  = (__half*)(g_scratch + OFF_WCTX);
    __half* Wihp  = (__half*)(g_scratch + OFF_WIH);
    __half* Wcomb = (__half*)(g_scratch + OFF_WCOMB);
    float*  bcat  = g_scratch + OFF_BCAT;
    float*  brec  = g_scratch + OFF_BREC;
    __half* ench  = (__half*)(g_scratch + OFF_ENC_H);
    __half* embg  = (__half*)(g_scratch + OFF_EMBG);
    __half* wfch  = (__half*)(g_scratch + OFF_WFC_H);
    __half* weah  = (__half*)(g_scratch + OFF_WEA_H);
    __half* w0    = (__half*)(g_scratch + OFF_W0);
    float*  b0    = g_scratch + OFF_B0;
    __half* mean  = (__half*)(g_scratch + OFF_MEAN);

    int i = blockIdx.x * blockDim.x + threadIdx.x;
    int stride = gridDim.x * blockDim.x;

    if (i == 0) { g_c_attdec = 0; g_c_pre = 0; g_c_step = 0; }

    for (int idx = i; idx < 1024 * 1024; idx += stride) {
        int r = idx >> 10, c = idx & 1023;
        Wcomb[(size_t)r * 5120 + c] =
            __float2half_rn((c < 512) ? Wdec[r * 512 + c] : Wfb[r * 512 + (c - 512)]);
    }
    for (int idx = i; idx < 1024; idx += stride)
        bcat[idx] = (idx < 512) ? bdec[idx] : bfb[idx - 512];

    for (int s = i; s < 1024 * 4096; s += stride) {
        int r = s >> 12, oc = s & 4095;
        int q = oc >> 10, j = oc & 1023;
        Wcomb[(size_t)r * 5120 + 1024 + j * 4 + q] = __float2half_rn(Whh[s]);
    }
    for (int s = i; s < 512 * 4096; s += stride) {
        int r = s >> 12, oc = s & 4095;
        int q = oc >> 10, j = oc & 1023;
        Wctx[(size_t)r * 4096 + j * 4 + q] = __float2half_rn(Wih[1024 * 4096 + s]);
    }
    for (int s = i; s < 1024 * 4096; s += stride) {
        int r = s >> 12, oc = s & 4095;
        int q = oc >> 10, j = oc & 1023;
        Wihp[(size_t)r * 4096 + j * 4 + q] = __float2half_rn(Wih[s]);
    }
    for (int idx = i; idx < 4096; idx += stride) {
        int j = idx >> 2, q = idx & 3;
        brec[idx] = bih[q * 1024 + j] + bhh[q * 1024 + j];
    }
    for (int idx = i; idx < (BB * PP * ENC) / 2; idx += stride) {
        float2 v = ((const float2*)enc)[idx];
        ((__half2*)ench)[idx] = __floats2half2_rn(v.x, v.y);
    }
    for (int idx = i; idx < TT * BB * EE; idx += stride) {
        int m = idx >> 10, c = idx & 1023;
        int tt = m >> 6, bb = m & 63;
        embg[idx] = __float2half_rn(emb[(size_t)caps[bb * LL + tt] * EE + c]);
    }
    for (int idx = i; idx < (HH * VV) / 2; idx += stride) {
        float2 v = ((const float2*)Wfc)[idx];
        ((__half2*)wfch)[idx] = __floats2half2_rn(v.x, v.y);
    }
    for (int idx = i; idx < ENC * AA; idx += stride) weah[idx] = __float2half_rn(Wea[idx]);
    for (int idx = i; idx < 512 * 2048; idx += stride) {
        int r = idx >> 11, c = idx & 2047;
        w0[idx] = __float2half_rn((c < 1024) ? Wih0[r * 1024 + c] : Wic0[r * 1024 + (c - 1024)]);
    }
    for (int idx = i; idx < 2048; idx += stride)
        b0[idx] = (idx < 1024) ? bih0[idx] : bic0[idx - 1024];
    for (int idx = i; idx < BB * ENC; idx += stride) {
        int b = idx >> 9, e = idx & 511;
        float s = 0.f;
        const float* base = enc + (size_t)(b * PP) * ENC + e;
        #pragma unroll 4
        for (int p = 0; p < PP; ++p) s += base[(size_t)p * ENC];
        mean[idx] = __float2half_rn(s * (1.f / (float)PP));
    }
}

// ====== gemm2 fp16: 128x128 tile, 8 warps (32x64), cp.async 4-stage ======
// CMODE 0: fp32 C; 1: preds remap; 2: init split; 3: half C
#define NS   4
#define G2ASTR 40
#define G2BSTR 136
#define G2ASZ (128 * G2ASTR)
#define G2BSZ (32 * G2BSTR)
#define G2STG (G2ASZ + G2BSZ)
#define G2_SMEM_BYTES (NS * G2STG * 2)

template<int CMODE>
__global__ __launch_bounds__(256, 2)
void gemm2(const __half* __restrict__ A, int lda,
           const __half* __restrict__ B, int ldb,
           float* __restrict__ C, int ldc,
           const float* __restrict__ bias,
           int M, int N, int K)
{
    extern __shared__ __half dynh[];
    float* dynf = (float*)dynh;

    const int tid = threadIdx.x;
    const int n0 = blockIdx.x * 128;
    const int m0 = blockIdx.y * 128;

    const __half* arow[2];
    const __half* brow[2];
    int bval[2];
    #pragma unroll
    for (int i = 0; i < 2; ++i) {
        int q = tid + i * 256;
        int r = q >> 2;
        int gr = m0 + r; if (gr >= M) gr = M - 1;
        arow[i] = A + (size_t)gr * lda + (q & 3) * 8;
        int br = q >> 4;
        int bcn = (q & 15) * 8;
        brow[i] = B + (size_t)br * ldb + n0 + bcn;
        bval[i] = (n0 + bcn) < N;
    }
    const unsigned int sbase = (unsigned int)__cvta_generic_to_shared(dynh);

    auto load_stage = [&](int kt, int s) {
        const unsigned int so = sbase + (unsigned int)(s * G2STG) * 2u;
        const int k0 = kt * 32;
        #pragma unroll
        for (int i = 0; i < 2; ++i) {
            int q = tid + i * 256;
            int r = q >> 2, c = (q & 3) * 8;
            cp16(so + (unsigned int)(r * G2ASTR + c) * 2u, arow[i] + k0, 1);
        }
        #pragma unroll
        for (int i = 0; i < 2; ++i) {
            int q = tid + i * 256;
            int br = q >> 4, bcn = (q & 15) * 8;
            cp16(so + (unsigned int)(G2ASZ + br * G2BSTR + bcn) * 2u,
                 brow[i] + (size_t)k0 * ldb, bval[i]);
        }
        asm volatile("cp.async.commit_group;\n" ::: "memory");
    };

    const int nk = K >> 5;
    #pragma unroll
    for (int s = 0; s < NS - 1; ++s) load_stage(s, s);

    const int wid = tid >> 5;
    const int wr = wid & 3;
    const int wc = wid >> 2;

    wmma::fragment<wmma::accumulator, 16, 16, 16, float> acc[2][4];
    #pragma unroll
    for (int i = 0; i < 2; ++i)
        #pragma unroll
        for (int j = 0; j < 4; ++j) wmma::fill_fragment(acc[i][j], 0.f);

    for (int kt = 0; kt < nk; ++kt) {
        asm volatile("cp.async.wait_group 2;\n" ::: "memory");
        __syncthreads();

        if (kt + NS - 1 < nk) load_stage(kt + NS - 1, (kt + NS - 1) % NS);
        else asm volatile("cp.async.commit_group;\n" ::: "memory");

        const __half* Ab = dynh + (kt % NS) * G2STG;
        const __half* Bb = Ab + G2ASZ;
        #pragma unroll
        for (int ks = 0; ks < 2; ++ks) {
            wmma::fragment<wmma::matrix_a, 16, 16, 16, __half, wmma::row_major> af[2];
            #pragma unroll
            for (int i = 0; i < 2; ++i)
                wmma::load_matrix_sync(af[i], Ab + (wr * 32 + i * 16) * G2ASTR + ks * 16, G2ASTR);
            #pragma unroll
            for (int j = 0; j < 4; ++j) {
                wmma::fragment<wmma::matrix_b, 16, 16, 16, __half, wmma::row_major> bf;
                wmma::load_matrix_sync(bf, Bb + (ks * 16) * G2BSTR + wc * 64 + j * 16, G2BSTR);
                wmma::mma_sync(acc[0][j], af[0], bf, acc[0][j]);
                wmma::mma_sync(acc[1][j], af[1], bf, acc[1][j]);
            }
        }
    }
    asm volatile("cp.async.wait_group 0;\n" ::: "memory");
    __syncthreads();

    float* Cs = dynf;
    for (int chunk = 0; chunk < 4; ++chunk) {
        if (wr == chunk) {
            #pragma unroll
            for (int i = 0; i < 2; ++i)
                #pragma unroll
                for (int j = 0; j < 4; ++j)
                    wmma::store_matrix_sync(Cs + (i * 16) * 132 + wc * 64 + j * 16,
                                            acc[i][j], 132, wmma::mem_row_major);
        }
        __syncthreads();
        #pragma unroll
        for (int it = 0; it < 16; ++it) {
            int idx = tid + it * 256;
            int r = idx >> 7, cn = idx & 127;
            int m = m0 + chunk * 32 + r;
            int n = n0 + cn;
            if (m < M && n < N) {
                float v = Cs[r * 132 + cn] + bias[n];
                if (CMODE == 0) {
                    C[(size_t)m * ldc + n] = v;
                } else if (CMODE == 1) {
                    int bb = m & 63, tt = m >> 6;
                    C[((size_t)bb * TT + tt) * ldc + n] = v;
                } else if (CMODE == 3) {
                    ((__half*)C)[(size_t)m * ldc + n] = __float2half_rn(v);
                } else {
                    if (n < 1024)
                        ((__half*)(g_scratch + OFF_SX))[(unsigned)m * 1536u + 512u + (unsigned)n] = __float2half_rn(v);
                    else
                        g_scratch[OFF_C + (unsigned)m * 1024u + (unsigned)(n - 1024)] = v;
                }
            }
        }
        __syncthreads();
    }
}

// ====== gemm3 fp16: 128x256 tile, 8 warps (64x64), cp.async 3-stage ======
// CMODE 0: fp32 C;  1: preds remap
#define G3NS 3
#define G3ASTR 40
#define G3BSTR 264
#define G3ASZ (128 * G3ASTR)      // 5120 halves
#define G3BSZ (32 * G3BSTR)       // 8448 halves
#define G3STG (G3ASZ + G3BSZ)     // 13568 halves
#define G3_SMEM_BYTES (G3NS * G3STG * 2)   // 81408

template<int CMODE>
__global__ __launch_bounds__(256, 1)
void gemm3(const __half* __restrict__ A, int lda,
           const __half* __restrict__ B, int ldb,
           float* __restrict__ C, int ldc,
           const float* __restrict__ bias,
           int M, int N, int K)
{
    extern __shared__ __half dynh[];
    float* dynf = (float*)dynh;

    const int tid = threadIdx.x;
    const int n0 = blockIdx.x * 256;
    const int m0 = blockIdx.y * 128;

    const __half* arow[2];
    const __half* brow[4];
    int bval[4];
    #pragma unroll
    for (int i = 0; i < 2; ++i) {
        int q = tid + i * 256;
        int r = q >> 2;
        int gr = m0 + r; if (gr >= M) gr = M - 1;
        arow[i] = A + (size_t)gr * lda + (q & 3) * 8;
    }
    #pragma unroll
    for (int i = 0; i < 4; ++i) {
        int q = tid + i * 256;
        int br = q >> 5;                // 0..31
        int bcn = (q & 31) * 8;         // 0..248
        brow[i] = B + (size_t)br * ldb + n0 + bcn;
        bval[i] = (n0 + bcn) < N;
    }
    const unsigned int sbase = (unsigned int)__cvta_generic_to_shared(dynh);

    auto load_stage = [&](int kt, int s) {
        const unsigned int so = sbase + (unsigned int)(s * G3STG) * 2u;
        const int k0 = kt * 32;
        #pragma unroll
        for (int i = 0; i < 2; ++i) {
            int q = tid + i * 256;
            int r = q >> 2, c = (q & 3) * 8;
            cp16(so + (unsigned int)(r * G3ASTR + c) * 2u, arow[i] + k0, 1);
        }
        #pragma unroll
        for (int i = 0; i < 4; ++i) {
            int q = tid + i * 256;
            int br = q >> 5, bcn = (q & 31) * 8;
            cp16(so + (unsigned int)(G3ASZ + br * G3BSTR + bcn) * 2u,
                 brow[i] + (size_t)k0 * ldb, bval[i]);
        }
        asm volatile("cp.async.commit_group;\n" ::: "memory");
    };

    const int nk = K >> 5;
    load_stage(0, 0);
    load_stage(1, 1);

    const int wid = tid >> 5;
    const int wm = wid & 1;     // 2 m-halves of 64
    const int wn = wid >> 1;    // 4 n-quarters of 64

    wmma::fragment<wmma::accumulator, 16, 16, 16, float> acc[4][4];
    #pragma unroll
    for (int i = 0; i < 4; ++i)
        #pragma unroll
        for (int j = 0; j < 4; ++j) wmma::fill_fragment(acc[i][j], 0.f);

    for (int kt = 0; kt < nk; ++kt) {
        asm volatile("cp.async.wait_group 1;\n" ::: "memory");
        __syncthreads();

        if (kt + 2 < nk) load_stage(kt + 2, (kt + 2) % G3NS);
        else asm volatile("cp.async.commit_group;\n" ::: "memory");

        const __half* Ab = dynh + (kt % G3NS) * G3STG;
        const __half* Bb = Ab + G3ASZ;
        #pragma unroll
        for (int ks = 0; ks < 2; ++ks) {
            wmma::fragment<wmma::matrix_a, 16, 16, 16, __half, wmma::row_major> af[4];
            #pragma unroll
            for (int i = 0; i < 4; ++i)
                wmma::load_matrix_sync(af[i], Ab + (wm * 64 + i * 16) * G3ASTR + ks * 16, G3ASTR);
            #pragma unroll
            for (int j = 0; j < 4; ++j) {
                wmma::fragment<wmma::matrix_b, 16, 16, 16, __half, wmma::row_major> bf;
                wmma::load_matrix_sync(bf, Bb + (ks * 16) * G3BSTR + wn * 64 + j * 16, G3BSTR);
                #pragma unroll
                for (int i = 0; i < 4; ++i)
                    wmma::mma_sync(acc[i][j], af[i], bf, acc[i][j]);
            }
        }
    }
    asm volatile("cp.async.wait_group 0;\n" ::: "memory");
    __syncthreads();

    // epilogue: 8 chunks of 16 rows; row group g owned by warps with wm==g>>2, frag i==g&3
    float* Cs = dynf;   // 16 x G3BSTR fp32
    for (int g = 0; g < 8; ++g) {
        if (wm == (g >> 2)) {
            int i = g & 3;
            #pragma unroll
            for (int j = 0; j < 4; ++j)
                wmma::store_matrix_sync(Cs + wn * 64 + j * 16, acc[i][j], G3BSTR, wmma::mem_row_major);
        }
        __syncthreads();
        #pragma unroll
        for (int it = 0; it < 16; ++it) {
            int idx = tid + it * 256;
            int r = idx >> 8, cn = idx & 255;
            int m = m0 + g * 16 + r;
            int n = n0 + cn;
            if (m < M && n < N) {
                float v = Cs[r * G3BSTR + cn] + bias[n];
                if (CMODE == 0) {
                    C[(size_t)m * ldc + n] = v;
                } else {
                    int bb = m & 63, tt = m >> 6;
                    C[((size_t)bb * TT + tt) * ldc + n] = v;
                }
            }
        }
        __syncthreads();
    }
}

// ================= persistent recurrence kernel =================
#define NBLK 128
#define RASTR 72
#define RBSTR 40
#define RASZ (64 * RASTR)
#define RBSZ (64 * RBSTR)
#define RSTG (RASZ + RBSZ)           // 7168 halves
#define R2STG (64 * 72 * 2)          // 9216 halves
#define RSMEM_BYTES (3 * R2STG * 2)  // 55296

// ---- 64x64 output tile, K-block 64, cp.async 3-stage ----
__device__ __forceinline__ void tile_gemm_64x64(
    const __half* __restrict__ A, int lda,
    const __half* __restrict__ B, int ldb, int K,
    __half* sbufh,
    wmma::fragment<wmma::accumulator, 16, 16, 16, float>& acc0,
    wmma::fragment<wmma::accumulator, 16, 16, 16, float>& acc1)
{
    const int tid = threadIdx.x;
    const int wid = tid >> 5;
    const int wm = wid & 1;
    const int wn = wid >> 1;
    const unsigned int sb = (unsigned int)__cvta_generic_to_shared(sbufh);
    const int nk = K >> 6;

    auto load_stage = [&](int kt, int s) {
        const unsigned int so = sb + (unsigned int)(s * R2STG) * 2u;
        const int k0 = kt * 64;
        #pragma unroll
        for (int i = 0; i < 2; ++i) {
            int q = tid + i * 256;
            int r = q >> 3, c = (q & 7) * 8;
            cp16(so + (unsigned int)(r * 72 + c) * 2u, A + (size_t)r * lda + k0 + c, 1);
        }
        #pragma unroll
        for (int i = 0; i < 2; ++i) {
            int q = tid + i * 256;
            int r = q >> 3, c = (q & 7) * 8;
            cp16(so + (unsigned int)(4608 + r * 72 + c) * 2u,
                 B + (size_t)(k0 + r) * ldb + c, 1);
        }
        asm volatile("cp.async.commit_group;\n" ::: "memory");
    };

    load_stage(0, 0);
    load_stage(1, 1);

    for (int kt = 0; kt < nk; ++kt) {
        asm volatile("cp.async.wait_group 1;\n" ::: "memory");
        __syncthreads();
        if (kt + 2 < nk) load_stage(kt + 2, (kt + 2) % 3);
        else asm volatile("cp.async.commit_group;\n" ::: "memory");

        const __half* Ab = sbufh + (kt % 3) * R2STG;
        const __half* Bb = Ab + 4608;
        #pragma unroll
        for (int kk = 0; kk < 4; ++kk) {
            int k = kk * 16;
            wmma::fragment<wmma::matrix_a, 16, 16, 16, __half, wmma::row_major> af0, af1;
            wmma::fragment<wmma::matrix_b, 16, 16, 16, __half, wmma::row_major> bf;
            wmma::load_matrix_sync(af0, Ab + (wm * 32) * 72 + k, 72);
            wmma::load_matrix_sync(af1, Ab + (wm * 32 + 16) * 72 + k, 72);
            wmma::load_matrix_sync(bf, Bb + k * 72 + wn * 16, 72);
            wmma::mma_sync(acc0, af0, bf, acc0);
            wmma::mma_sync(acc1, af1, bf, acc1);
        }
    }
    asm volatile("cp.async.wait_group 0;\n" ::: "memory");
    __syncthreads();
}

// ---- 64x32 output tile, K-block 64, warp K-split (2 groups) ----
__device__ __forceinline__ void tile_gemm_ws(
    const __half* __restrict__ A, int lda,
    const __half* __restrict__ B, int ldb, int K,
    __half* sbufh,
    wmma::fragment<wmma::accumulator, 16, 16, 16, float>& acc0,
    wmma::fragment<wmma::accumulator, 16, 16, 16, float>& acc1)
{
    const int tid = threadIdx.x;
    const int wid = tid >> 5;
    const int kg = wid >> 2;
    const int nh = (wid >> 1) & 1;
    const int mh = wid & 1;
    const unsigned int sb = (unsigned int)__cvta_generic_to_shared(sbufh);
    const int nk = K >> 6;

    auto load_stage = [&](int kt, int s) {
        const unsigned int so = sb + (unsigned int)(s * RSTG) * 2u;
        const int k0 = kt * 64;
        #pragma unroll
        for (int i = 0; i < 2; ++i) {
            int q = tid + i * 256;
            int r = q >> 3, c = (q & 7) * 8;
            cp16(so + (unsigned int)(r * RASTR + c) * 2u, A + (size_t)r * lda + k0 + c, 1);
        }
        {
            int r = tid >> 2, c = (tid & 3) * 8;
            cp16(so + (unsigned int)(RASZ + r * RBSTR + c) * 2u,
                 B + (size_t)(k0 + r) * ldb + c, 1);
        }
        asm volatile("cp.async.commit_group;\n" ::: "memory");
    };

    load_stage(0, 0);
    load_stage(1, 1);

    for (int kt = 0; kt < nk; ++kt) {
        asm volatile("cp.async.wait_group 1;\n" ::: "memory");
        __syncthreads();
        if (kt + 2 < nk) load_stage(kt + 2, (kt + 2) % 3);
        else asm volatile("cp.async.commit_group;\n" ::: "memory");

        const __half* Ab = sbufh + (kt % 3) * RSTG;
        const __half* Bb = Ab + RASZ;
        #pragma unroll
        for (int kk = 0; kk < 2; ++kk) {
            int k = kg * 32 + kk * 16;
            wmma::fragment<wmma::matrix_a, 16, 16, 16, __half, wmma::row_major> af0, af1;
            wmma::fragment<wmma::matrix_b, 16, 16, 16, __half, wmma::row_major> bf;
            wmma::load_matrix_sync(af0, Ab + (mh * 32) * RASTR + k, RASTR);
            wmma::load_matrix_sync(af1, Ab + (mh * 32 + 16) * RASTR + k, RASTR);
            wmma::load_matrix_sync(bf, Bb + k * RBSTR + nh * 16, RBSTR);
            wmma::mma_sync(acc0, af0, bf, acc0);
            wmma::mma_sync(acc1, af1, bf, acc1);
        }
    }
    asm volatile("cp.async.wait_group 0;\n" ::: "memory");
    __syncthreads();
}

__device__ __forceinline__ float sigm(float x) { return 1.f / (1.f + expf(-x)); }

__device__ __forceinline__ void comb_tile(
    const __half* __restrict__ h, const __half* __restrict__ Wcomb,
    float* __restrict__ comb, const float* __restrict__ bcat,
    int n0, __half* sbufh, float* sbuff)
{
    wmma::fragment<wmma::accumulator, 16, 16, 16, float> a0, a1;
    wmma::fill_fragment(a0, 0.f);
    wmma::fill_fragment(a1, 0.f);
    tile_gemm_64x64(h, 1536, Wcomb + n0, 5120, HH, sbufh, a0, a1);
    {
        const int wid = threadIdx.x >> 5;
        const int wm = wid & 1, wn = wid >> 1;
        wmma::store_matrix_sync(sbuff + (wm * 32) * 68 + wn * 16, a0, 68, wmma::mem_row_major);
        wmma::store_matrix_sync(sbuff + (wm * 32 + 16) * 68 + wn * 16, a1, 68, wmma::mem_row_major);
    }
    __syncthreads();
    const bool isAtt = (n0 < 1024);
    #pragma unroll
    for (int it = 0; it < 16; ++it) {
        int idx = threadIdx.x + it * 256;
        int r = idx >> 6, c = idx & 63;
        float v = sbuff[r * 68 + c];
        if (isAtt) v += bcat[n0 + c];
        comb[(size_t)r * 5120 + n0 + c] = v;
    }
    __syncthreads();
}

__global__ __launch_bounds__(256, 1)
void recur_kernel(const float* __restrict__ wfull,
                  const float* __restrict__ bfull,
                  float* __restrict__ alpha_out)
{
    extern __shared__ __half sbufh[];
    float* sbuff = (float*)sbufh;

    const int bi = blockIdx.x;
    const int tid = threadIdx.x;
    const int wid = tid >> 5, lane = tid & 31;

    float* S = g_scratch;
    const __half* att_ench = (const __half*)(S + OFF_ATT_ENC);
    const __half* ench     = (const __half*)(S + OFF_ENC_H);
    const __half* Wcomb    = (const __half*)(S + OFF_WCOMB);
    const __half* Wctx     = (const __half*)(S + OFF_WCTX);
    const float*  bcat     = S + OFF_BCAT;
    const float*  ebias    = S + OFF_EBIAS;
    __half* sxh            = (__half*)(S + OFF_SX);
    float* cbuf            = S + OFF_C;
    float* comb            = S + OFF_COMB;
    __half* hall           = (__half*)(S + OFF_HALL);

    const float bf0 = bfull[0];

    for (int t = 0; t < TT; ++t) {
        const int cur = t & 1, nxt = cur ^ 1;
        __half* sxc = sxh + cur * (64 * 1536);
        __half* sxn = sxh + nxt * (64 * 1536);
        const unsigned tgt16 = 16u * (unsigned)(t + 1);
        const unsigned tgt128 = 128u * (unsigned)(t + 1);

        if (bi >= 64) {
            int tile = bi - 64;
            if (tile < 16) {
                comb_tile(sxc + 512, Wcomb, comb, bcat, tile * 64, sbufh, sbuff);
                bar_arrive(&g_c_attdec);
                comb_tile(sxc + 512, Wcomb, comb, bcat, 1024 + (48 + tile) * 64, sbufh, sbuff);
            } else {
                comb_tile(sxc + 512, Wcomb, comb, bcat, 1024 + (tile - 16) * 64, sbufh, sbuff);
            }
            bar_arrive(&g_c_pre);
            bar_wait(&g_c_pre, tgt128);
        } else {
            bar_wait(&g_c_attdec, tgt16);
            const int b = bi;
            float* sa   = sbuff;
            float* sw   = sbuff + 512;
            float* se   = sbuff + 1024;
            float* sred = sbuff + 1248;
            float* sctx = sbuff + 1280;

            for (int i = tid; i < AA; i += 256) {
                sa[i] = comb[(size_t)b * 5120 + i];
                sw[i] = wfull[i];
            }
            __syncthreads();

            for (int p = wid; p < PP; p += 8) {
                const __half2* row = (const __half2*)(att_ench + (size_t)(b * PP + p) * AA);
                float acc = 0.f;
                #pragma unroll 4
                for (int a2 = lane; a2 < 256; a2 += 32) {
                    __half2 hv = row[a2];
                    float x0 = __low2float(hv)  + sa[a2 * 2];
                    float x1 = __high2float(hv) + sa[a2 * 2 + 1];
                    x0 = fmaxf(x0, 0.f); x1 = fmaxf(x1, 0.f);
                    acc += x0 * sw[a2 * 2] + x1 * sw[a2 * 2 + 1];
                }
                #pragma unroll
                for (int o = 16; o; o >>= 1) acc += __shfl_xor_sync(0xffffffffu, acc, o);
                if (lane == 0) se[p] = acc + bf0;
            }
            __syncthreads();

            float v = (tid < PP) ? se[tid] : -1e30f;
            float m = v;
            #pragma unroll
            for (int o = 16; o; o >>= 1) m = fmaxf(m, __shfl_xor_sync(0xffffffffu, m, o));
            if (lane == 0) sred[wid] = m;
            __syncthreads();
            if (wid == 0) {
                float mm = (lane < 8) ? sred[lane] : -1e30f;
                #pragma unroll
                for (int o = 16; o; o >>= 1) mm = fmaxf(mm, __shfl_xor_sync(0xffffffffu, mm, o));
                if (lane == 0) sred[0] = mm;
            }
            __syncthreads();
            float mx = sred[0];
            __syncthreads();

            float ex = (tid < PP) ? expf(v - mx) : 0.f;
            float s = ex;
            #pragma unroll
            for (int o = 16; o; o >>= 1) s += __shfl_xor_sync(0xffffffffu, s, o);
            if (lane == 0) sred[wid] = s;
            __syncthreads();
            if (wid == 0) {
                float ss = (lane < 8) ? sred[lane] : 0.f;
                #pragma unroll
                for (int o = 16; o; o >>= 1) ss += __shfl_xor_sync(0xffffffffu, ss, o);
                if (lane == 0) sred[0] = ss;
            }
            __syncthreads();
            float inv = 1.f / sred[0];

            if (tid < PP) {
                float al = ex * inv;
                se[tid] = al;
                alpha_out[((size_t)b * TT + t) * PP + tid] = al;
            }
            __syncthreads();

            {
                int grp = tid >> 7;
                int t2 = tid & 127;
                const __half2* base =
                    (const __half2*)(ench + ((size_t)(b * PP) + grp * 98) * ENC) + t2 * 2;
                const float* al = se + grp * 98;
                float4 acc4 = make_float4(0.f, 0.f, 0.f, 0.f);
                #pragma unroll 7
                for (int p = 0; p < 98; ++p) {
                    float a = al[p];
                    __half2 v01 = base[(size_t)p * 256];
                    __half2 v23 = base[(size_t)p * 256 + 1];
                    acc4.x += a * __low2float(v01);  acc4.y += a * __high2float(v01);
                    acc4.z += a * __low2float(v23);  acc4.w += a * __high2float(v23);
                }
                *(float4*)&sctx[grp * 512 + t2 * 4] = acc4;
            }
            __syncthreads();
            if (tid < 128) {
                float4 c0 = *(float4*)&sctx[tid * 4];
                float4 c1 = *(float4*)&sctx[512 + tid * 4];
                const float* fb = comb + (size_t)b * 5120 + 512 + tid * 4;
                __half2 h01 = __floats2half2_rn(sigm(fb[0]) * (c0.x + c1.x),
                                                sigm(fb[1]) * (c0.y + c1.y));
                __half2 h23 = __floats2half2_rn(sigm(fb[2]) * (c0.z + c1.z),
                                                sigm(fb[3]) * (c0.w + c1.w));
                *(__half2*)&sxc[b * 1536 + tid * 4]     = h01;
                *(__half2*)&sxc[b * 1536 + tid * 4 + 2] = h23;
            }
            bar_arrive(&g_c_pre);
            bar_wait(&g_c_pre, tgt128);
        }

        // ---- Phase C ----
        {
            wmma::fragment<wmma::accumulator, 16, 16, 16, float> a0, a1;
            wmma::fill_fragment(a0, 0.f);
            wmma::fill_fragment(a1, 0.f);
            const int n0 = bi * 32;
            tile_gemm_ws(sxc, 1536, Wctx + n0, 4096, ENC, sbufh, a0, a1);
            {
                const int kg = wid >> 2;
                const int nh = (wid >> 1) & 1;
                const int mh = wid & 1;
                float* Cs = sbuff + kg * 2304;
                wmma::store_matrix_sync(Cs + (mh * 32) * 36 + nh * 16, a0, 36, wmma::mem_row_major);
                wmma::store_matrix_sync(Cs + (mh * 32 + 16) * 36 + nh * 16, a1, 36, wmma::mem_row_major);
            }
            __syncthreads();

            #pragma unroll
            for (int i = 0; i < 2; ++i) {
                int p = tid + i * 256;
                int b = p >> 3, jj = p & 7;
                int j = bi * 8 + jj;
                float4 g0 = *(float4*)&sbuff[b * 36 + jj * 4];
                float4 g1 = *(float4*)&sbuff[2304 + b * 36 + jj * 4];
                float4 hp = *(const float4*)&comb[(size_t)b * 5120 + 1024 + n0 + jj * 4];
                float4 e = *(const float4*)&ebias[((size_t)t * BB + b) * 4096 + n0 + jj * 4];
                float gi = g0.x + g1.x + hp.x + e.x, gf = g0.y + g1.y + hp.y + e.y;
                float gg = g0.z + g1.z + hp.z + e.z, go = g0.w + g1.w + hp.w + e.w;
                float co = cbuf[b * 1024 + j];
                float cn = sigm(gf) * co + sigm(gi) * tanhf(gg);
                float h  = sigm(go) * tanhf(cn);
                __half hr = __float2half_rn(h);
                cbuf[b * 1024 + j] = cn;
                sxn[b * 1536 + 512 + j] = hr;
                hall[((size_t)t * BB + b) * 1024 + j] = hr;
            }
        }
        bar_arrive(&g_c_step);
        bar_wait(&g_c_step, tgt128);
    }
}

// ---------------- launch ----------------
extern "C" void kernel_launch(void* const* d_in, const int* in_sizes, int n_in,
                              void* d_out, int out_size)
{
    const float* enc       = (const float*)d_in[0];
    const int*   caps      = (const int*)  d_in[1];
    const float* W_enc_att = (const float*)d_in[3];
    const float* b_enc_att = (const float*)d_in[4];
    const float* W_dec_att = (const float*)d_in[5];
    const float* b_dec_att = (const float*)d_in[6];
    const float* W_full    = (const float*)d_in[7];
    const float* b_full    = (const float*)d_in[8];
    const float* emb       = (const float*)d_in[9];
    const float* W_ih      = (const float*)d_in[10];
    const float* b_ih      = (const float*)d_in[11];
    const float* W_hh      = (const float*)d_in[12];
    const float* b_hh      = (const float*)d_in[13];
    const float* W_init_h  = (const float*)d_in[14];
    const float* b_init_h  = (const float*)d_in[15];
    const float* W_init_c  = (const float*)d_in[16];
    const float* b_init_c  = (const float*)d_in[17];
    const float* W_fbeta   = (const float*)d_in[18];
    const float* b_fbeta   = (const float*)d_in[19];
    const float* W_fc      = (const float*)d_in[20];
    const float* b_fc      = (const float*)d_in[21];

    float* out = (float*)d_out;
    float* alpha_out = out + (size_t)BB * TT * VV;

    void* sp = nullptr;
    cudaGetSymbolAddress(&sp, g_scratch);
    float* S = (float*)sp;

    cudaFuncSetAttribute(gemm2<2>, cudaFuncAttributeMaxDynamicSharedMemorySize, G2_SMEM_BYTES);
    cudaFuncSetAttribute(gemm2<3>, cudaFuncAttributeMaxDynamicSharedMemorySize, G2_SMEM_BYTES);
    cudaFuncSetAttribute(gemm3<0>, cudaFuncAttributeMaxDynamicSharedMemorySize, G3_SMEM_BYTES);
    cudaFuncSetAttribute(gemm3<1>, cudaFuncAttributeMaxDynamicSharedMemorySize, G3_SMEM_BYTES);
    cudaFuncSetAttribute(recur_kernel, cudaFuncAttributeMaxDynamicSharedMemorySize, RSMEM_BYTES);

    prep_kernel<<<2048, 256>>>(W_dec_att, W_fbeta, b_dec_att, b_fbeta, W_ih, W_hh, b_ih, b_hh,
                               enc, emb, W_fc, W_enc_att, W_init_h, W_init_c,
                               b_init_h, b_init_c, caps);

    // [h0 | c0]
    gemm2<2><<<dim3(16, 1), 256, G2_SMEM_BYTES>>>(
        (const __half*)(S + OFF_MEAN), ENC, (const __half*)(S + OFF_W0), 2048,
        S, 0, S + OFF_B0, BB, 2048, ENC);

    // att_enc (fp16 output)
    gemm2<3><<<dim3(4, 98), 256, G2_SMEM_BYTES>>>(
        (const __half*)(S + OFF_ENC_H), ENC, (const __half*)(S + OFF_WEA_H), AA,
        S + OFF_ATT_ENC, AA, b_enc_att, BB * PP, AA, ENC);

    // ebias (128x256 tiles)
    gemm3<0><<<dim3(16, 12), 256, G3_SMEM_BYTES>>>(
        (const __half*)(S + OFF_EMBG), EE, (const __half*)(S + OFF_WIH), 4096,
        S + OFF_EBIAS, 4096, S + OFF_BREC, TT * BB, 4096, EE);

    // persistent recurrence
    recur_kernel<<<NBLK, 256, RSMEM_BYTES>>>(W_full, b_full, alpha_out);

    // predictions (128x256 tiles)
    gemm3<1><<<dim3(79, 12), 256, G3_SMEM_BYTES>>>(
        (const __half*)(S + OFF_HALL), HH, (const __half*)(S + OFF_WFC_H), VV,
        out, VV, b_fc, TT * BB, VV, HH);
}

// round 14
// speedup vs baseline: 1.9849x; 1.9849x over previous
#include <cuda_runtime.h>
#include <cuda_fp16.h>
#include <mma.h>
#include <math.h>
#include <cstdint>

using namespace nvcuda;

// ---------------- problem constants ----------------
#define BB    64
#define PP    196
#define ENC   512
#define EE    1024
#define HH    1024
#define AA    512
#define VV    20000
#define LL    25
#define TT    24

// ---------------- scratch layout (float units; half regions cast) ----------------
#define OFF_ATT_ENC  0u            // half 12544*512
#define OFF_EBIAS    6422528u      // fp32 1536*4096
#define OFF_WCTX     12713984u     // half 512*4096  (W_ih rows 1024.., col-permuted)
#define OFF_WIH      13762560u     // half 1024*4096 (col-permuted)
#define OFF_WCOMB    15859712u     // half 1024*5120 ([Wcat | Whh_perm])
#define OFF_BCAT     18481152u     // fp32 1024
#define OFF_BREC     18482176u     // fp32 4096
#define OFF_MEAN     18486272u     // half 64*512
#define OFF_SX       18502656u     // half 2*64*1536 ([gc|h])
#define OFF_C        18600960u     // fp32 64*1024
#define OFF_COMB     18666496u     // fp32 64*5120 (attdec | fbeta | hpart)
#define OFF_HALL     18994176u     // half 1536*1024
#define OFF_ENC_H    19780608u     // half 12544*512
#define OFF_EMBG     22991872u     // half 1536*1024
#define OFF_WFC_H    23778304u     // half 1024*20000
#define OFF_WEA_H    34018304u     // half 512*512
#define OFF_W0       34149376u     // half 512*2048
#define OFF_B0       34673664u     // fp32 2048
#define SCRATCH_TOTAL 34675712u

__device__ __align__(256) float g_scratch[SCRATCH_TOTAL];

// monotonic counting barriers (reset by prep_kernel each launch)
__device__ unsigned g_c_attdec = 0;
__device__ unsigned g_c_pre    = 0;
__device__ unsigned g_c_step   = 0;

__device__ __forceinline__ void cp16(unsigned int dst, const void* src, int pred)
{
    asm volatile(
        "{\n\t.reg .pred p;\n\t"
        "setp.ne.b32 p, %2, 0;\n\t"
        "@p cp.async.cg.shared.global [%0], [%1], 16;\n\t}\n"
        :: "r"(dst), "l"(src), "r"(pred));
}

__device__ __forceinline__ void bar_arrive(unsigned* c)
{
    __syncthreads();
    if (threadIdx.x == 0) { __threadfence(); atomicAdd(c, 1u); }
}
__device__ __forceinline__ void bar_wait(unsigned* c, unsigned target)
{
    if (threadIdx.x == 0) {
        while (*(volatile unsigned*)c < target) {}
        __threadfence();
    }
    __syncthreads();
}

// ---------------- prep ----------------
__global__ void prep_kernel(const float* __restrict__ Wdec, const float* __restrict__ Wfb,
                            const float* __restrict__ bdec, const float* __restrict__ bfb,
                            const float* __restrict__ Wih,  const float* __restrict__ Whh,
                            const float* __restrict__ bih,  const float* __restrict__ bhh,
                            const float* __restrict__ enc,  const float* __restrict__ emb,
                            const float* __restrict__ Wfc,  const float* __restrict__ Wea,
                            const float* __restrict__ Wih0, const float* __restrict__ Wic0,
                            const float* __restrict__ bih0, const float* __restrict__ bic0,
                            const int*   __restrict__ caps)
{
    __half* Wctx  = (__half*)(g_scratch + OFF_WCTX);
    __half* Wihp  = (__half*)(g_scratch + OFF_WIH);
    __half* Wcomb = (__half*)(g_scratch + OFF_WCOMB);
    float*  bcat  = g_scratch + OFF_BCAT;
    float*  brec  = g_scratch + OFF_BREC;
    __half* ench  = (__half*)(g_scratch + OFF_ENC_H);
    __half* embg  = (__half*)(g_scratch + OFF_EMBG);
    __half* wfch  = (__half*)(g_scratch + OFF_WFC_H);
    __half* weah  = (__half*)(g_scratch + OFF_WEA_H);
    __half* w0    = (__half*)(g_scratch + OFF_W0);
    float*  b0    = g_scratch + OFF_B0;
    __half* mean  = (__half*)(g_scratch + OFF_MEAN);

    int i = blockIdx.x * blockDim.x + threadIdx.x;
    int stride = gridDim.x * blockDim.x;

    if (i == 0) { g_c_attdec = 0; g_c_pre = 0; g_c_step = 0; }

    for (int idx = i; idx < 1024 * 1024; idx += stride) {
        int r = idx >> 10, c = idx & 1023;
        Wcomb[(size_t)r * 5120 + c] =
            __float2half_rn((c < 512) ? Wdec[r * 512 + c] : Wfb[r * 512 + (c - 512)]);
    }
    for (int idx = i; idx < 1024; idx += stride)
        bcat[idx] = (idx < 512) ? bdec[idx] : bfb[idx - 512];

    for (int s = i; s < 1024 * 4096; s += stride) {
        int r = s >> 12, oc = s & 4095;
        int q = oc >> 10, j = oc & 1023;
        Wcomb[(size_t)r * 5120 + 1024 + j * 4 + q] = __float2half_rn(Whh[s]);
    }
    for (int s = i; s < 512 * 4096; s += stride) {
        int r = s >> 12, oc = s & 4095;
        int q = oc >> 10, j = oc & 1023;
        Wctx[(size_t)r * 4096 + j * 4 + q] = __float2half_rn(Wih[1024 * 4096 + s]);
    }
    for (int s = i; s < 1024 * 4096; s += stride) {
        int r = s >> 12, oc = s & 4095;
        int q = oc >> 10, j = oc & 1023;
        Wihp[(size_t)r * 4096 + j * 4 + q] = __float2half_rn(Wih[s]);
    }
    for (int idx = i; idx < 4096; idx += stride) {
        int j = idx >> 2, q = idx & 3;
        brec[idx] = bih[q * 1024 + j] + bhh[q * 1024 + j];
    }
    for (int idx = i; idx < (BB * PP * ENC) / 2; idx += stride) {
        float2 v = ((const float2*)enc)[idx];
        ((__half2*)ench)[idx] = __floats2half2_rn(v.x, v.y);
    }
    for (int idx = i; idx < TT * BB * EE; idx += stride) {
        int m = idx >> 10, c = idx & 1023;
        int tt = m >> 6, bb = m & 63;
        embg[idx] = __float2half_rn(emb[(size_t)caps[bb * LL + tt] * EE + c]);
    }
    for (int idx = i; idx < (HH * VV) / 2; idx += stride) {
        float2 v = ((const float2*)Wfc)[idx];
        ((__half2*)wfch)[idx] = __floats2half2_rn(v.x, v.y);
    }
    for (int idx = i; idx < ENC * AA; idx += stride) weah[idx] = __float2half_rn(Wea[idx]);
    for (int idx = i; idx < 512 * 2048; idx += stride) {
        int r = idx >> 11, c = idx & 2047;
        w0[idx] = __float2half_rn((c < 1024) ? Wih0[r * 1024 + c] : Wic0[r * 1024 + (c - 1024)]);
    }
    for (int idx = i; idx < 2048; idx += stride)
        b0[idx] = (idx < 1024) ? bih0[idx] : bic0[idx - 1024];
    for (int idx = i; idx < BB * ENC; idx += stride) {
        int b = idx >> 9, e = idx & 511;
        float s = 0.f;
        const float* base = enc + (size_t)(b * PP) * ENC + e;
        #pragma unroll 4
        for (int p = 0; p < PP; ++p) s += base[(size_t)p * ENC];
        mean[idx] = __float2half_rn(s * (1.f / (float)PP));
    }
}

// ====== gemm2 fp16: 128x128 tile, 8 warps (32x64), cp.async 4-stage ======
// CMODE 0: fp32 C; 1: preds remap; 2: init split; 3: half C
#define NS   4
#define G2ASTR 40
#define G2BSTR 136
#define G2ASZ (128 * G2ASTR)
#define G2BSZ (32 * G2BSTR)
#define G2STG (G2ASZ + G2BSZ)
#define G2_SMEM_BYTES (NS * G2STG * 2)

template<int CMODE>
__global__ __launch_bounds__(256, 2)
void gemm2(const __half* __restrict__ A, int lda,
           const __half* __restrict__ B, int ldb,
           float* __restrict__ C, int ldc,
           const float* __restrict__ bias,
           int M, int N, int K)
{
    extern __shared__ __half dynh[];
    float* dynf = (float*)dynh;

    const int tid = threadIdx.x;
    const int n0 = blockIdx.x * 128;
    const int m0 = blockIdx.y * 128;

    const __half* arow[2];
    const __half* brow[2];
    int bval[2];
    #pragma unroll
    for (int i = 0; i < 2; ++i) {
        int q = tid + i * 256;
        int r = q >> 2;
        int gr = m0 + r; if (gr >= M) gr = M - 1;
        arow[i] = A + (size_t)gr * lda + (q & 3) * 8;
        int br = q >> 4;
        int bcn = (q & 15) * 8;
        brow[i] = B + (size_t)br * ldb + n0 + bcn;
        bval[i] = (n0 + bcn) < N;
    }
    const unsigned int sbase = (unsigned int)__cvta_generic_to_shared(dynh);

    auto load_stage = [&](int kt, int s) {
        const unsigned int so = sbase + (unsigned int)(s * G2STG) * 2u;
        const int k0 = kt * 32;
        #pragma unroll
        for (int i = 0; i < 2; ++i) {
            int q = tid + i * 256;
            int r = q >> 2, c = (q & 3) * 8;
            cp16(so + (unsigned int)(r * G2ASTR + c) * 2u, arow[i] + k0, 1);
        }
        #pragma unroll
        for (int i = 0; i < 2; ++i) {
            int q = tid + i * 256;
            int br = q >> 4, bcn = (q & 15) * 8;
            cp16(so + (unsigned int)(G2ASZ + br * G2BSTR + bcn) * 2u,
                 brow[i] + (size_t)k0 * ldb, bval[i]);
        }
        asm volatile("cp.async.commit_group;\n" ::: "memory");
    };

    const int nk = K >> 5;
    #pragma unroll
    for (int s = 0; s < NS - 1; ++s) load_stage(s, s);

    const int wid = tid >> 5;
    const int wr = wid & 3;
    const int wc = wid >> 2;

    wmma::fragment<wmma::accumulator, 16, 16, 16, float> acc[2][4];
    #pragma unroll
    for (int i = 0; i < 2; ++i)
        #pragma unroll
        for (int j = 0; j < 4; ++j) wmma::fill_fragment(acc[i][j], 0.f);

    for (int kt = 0; kt < nk; ++kt) {
        asm volatile("cp.async.wait_group 2;\n" ::: "memory");
        __syncthreads();

        if (kt + NS - 1 < nk) load_stage(kt + NS - 1, (kt + NS - 1) % NS);
        else asm volatile("cp.async.commit_group;\n" ::: "memory");

        const __half* Ab = dynh + (kt % NS) * G2STG;
        const __half* Bb = Ab + G2ASZ;
        #pragma unroll
        for (int ks = 0; ks < 2; ++ks) {
            wmma::fragment<wmma::matrix_a, 16, 16, 16, __half, wmma::row_major> af[2];
            #pragma unroll
            for (int i = 0; i < 2; ++i)
                wmma::load_matrix_sync(af[i], Ab + (wr * 32 + i * 16) * G2ASTR + ks * 16, G2ASTR);
            #pragma unroll
            for (int j = 0; j < 4; ++j) {
                wmma::fragment<wmma::matrix_b, 16, 16, 16, __half, wmma::row_major> bf;
                wmma::load_matrix_sync(bf, Bb + (ks * 16) * G2BSTR + wc * 64 + j * 16, G2BSTR);
                wmma::mma_sync(acc[0][j], af[0], bf, acc[0][j]);
                wmma::mma_sync(acc[1][j], af[1], bf, acc[1][j]);
            }
        }
    }
    asm volatile("cp.async.wait_group 0;\n" ::: "memory");
    __syncthreads();

    float* Cs = dynf;
    for (int chunk = 0; chunk < 4; ++chunk) {
        if (wr == chunk) {
            #pragma unroll
            for (int i = 0; i < 2; ++i)
                #pragma unroll
                for (int j = 0; j < 4; ++j)
                    wmma::store_matrix_sync(Cs + (i * 16) * 132 + wc * 64 + j * 16,
                                            acc[i][j], 132, wmma::mem_row_major);
        }
        __syncthreads();
        #pragma unroll
        for (int it = 0; it < 16; ++it) {
            int idx = tid + it * 256;
            int r = idx >> 7, cn = idx & 127;
            int m = m0 + chunk * 32 + r;
            int n = n0 + cn;
            if (m < M && n < N) {
                float v = Cs[r * 132 + cn] + bias[n];
                if (CMODE == 0) {
                    C[(size_t)m * ldc + n] = v;
                } else if (CMODE == 1) {
                    int bb = m & 63, tt = m >> 6;
                    C[((size_t)bb * TT + tt) * ldc + n] = v;
                } else if (CMODE == 3) {
                    ((__half*)C)[(size_t)m * ldc + n] = __float2half_rn(v);
                } else {
                    if (n < 1024)
                        ((__half*)(g_scratch + OFF_SX))[(unsigned)m * 1536u + 512u + (unsigned)n] = __float2half_rn(v);
                    else
                        g_scratch[OFF_C + (unsigned)m * 1024u + (unsigned)(n - 1024)] = v;
                }
            }
        }
        __syncthreads();
    }
}

// ================= persistent recurrence kernel =================
#define NBLK 128
#define RASTR 72
#define RBSTR 40
#define RASZ (64 * RASTR)
#define RBSZ (64 * RBSTR)
#define RSTG (RASZ + RBSZ)           // 7168 halves
#define R2STG (64 * 72 * 2)          // 9216 halves
#define RSMEM_BYTES (3 * R2STG * 2)  // 55296

// ---- 64x64 output tile, K-block 64, cp.async 3-stage ----
__device__ __forceinline__ void tile_gemm_64x64(
    const __half* __restrict__ A, int lda,
    const __half* __restrict__ B, int ldb, int K,
    __half* sbufh,
    wmma::fragment<wmma::accumulator, 16, 16, 16, float>& acc0,
    wmma::fragment<wmma::accumulator, 16, 16, 16, float>& acc1)
{
    const int tid = threadIdx.x;
    const int wid = tid >> 5;
    const int wm = wid & 1;
    const int wn = wid >> 1;
    const unsigned int sb = (unsigned int)__cvta_generic_to_shared(sbufh);
    const int nk = K >> 6;

    auto load_stage = [&](int kt, int s) {
        const unsigned int so = sb + (unsigned int)(s * R2STG) * 2u;
        const int k0 = kt * 64;
        #pragma unroll
        for (int i = 0; i < 2; ++i) {
            int q = tid + i * 256;
            int r = q >> 3, c = (q & 7) * 8;
            cp16(so + (unsigned int)(r * 72 + c) * 2u, A + (size_t)r * lda + k0 + c, 1);
        }
        #pragma unroll
        for (int i = 0; i < 2; ++i) {
            int q = tid + i * 256;
            int r = q >> 3, c = (q & 7) * 8;
            cp16(so + (unsigned int)(4608 + r * 72 + c) * 2u,
                 B + (size_t)(k0 + r) * ldb + c, 1);
        }
        asm volatile("cp.async.commit_group;\n" ::: "memory");
    };

    load_stage(0, 0);
    load_stage(1, 1);

    for (int kt = 0; kt < nk; ++kt) {
        asm volatile("cp.async.wait_group 1;\n" ::: "memory");
        __syncthreads();
        if (kt + 2 < nk) load_stage(kt + 2, (kt + 2) % 3);
        else asm volatile("cp.async.commit_group;\n" ::: "memory");

        const __half* Ab = sbufh + (kt % 3) * R2STG;
        const __half* Bb = Ab + 4608;
        #pragma unroll
        for (int kk = 0; kk < 4; ++kk) {
            int k = kk * 16;
            wmma::fragment<wmma::matrix_a, 16, 16, 16, __half, wmma::row_major> af0, af1;
            wmma::fragment<wmma::matrix_b, 16, 16, 16, __half, wmma::row_major> bf;
            wmma::load_matrix_sync(af0, Ab + (wm * 32) * 72 + k, 72);
            wmma::load_matrix_sync(af1, Ab + (wm * 32 + 16) * 72 + k, 72);
            wmma::load_matrix_sync(bf, Bb + k * 72 + wn * 16, 72);
            wmma::mma_sync(acc0, af0, bf, acc0);
            wmma::mma_sync(acc1, af1, bf, acc1);
        }
    }
    asm volatile("cp.async.wait_group 0;\n" ::: "memory");
    __syncthreads();
}

// ---- 64x32 output tile, K-block 64, warp K-split (2 groups) ----
__device__ __forceinline__ void tile_gemm_ws(
    const __half* __restrict__ A, int lda,
    const __half* __restrict__ B, int ldb, int K,
    __half* sbufh,
    wmma::fragment<wmma::accumulator, 16, 16, 16, float>& acc0,
    wmma::fragment<wmma::accumulator, 16, 16, 16, float>& acc1)
{
    const int tid = threadIdx.x;
    const int wid = tid >> 5;
    const int kg = wid >> 2;
    const int nh = (wid >> 1) & 1;
    const int mh = wid & 1;
    const unsigned int sb = (unsigned int)__cvta_generic_to_shared(sbufh);
    const int nk = K >> 6;

    auto load_stage = [&](int kt, int s) {
        const unsigned int so = sb + (unsigned int)(s * RSTG) * 2u;
        const int k0 = kt * 64;
        #pragma unroll
        for (int i = 0; i < 2; ++i) {
            int q = tid + i * 256;
            int r = q >> 3, c = (q & 7) * 8;
            cp16(so + (unsigned int)(r * RASTR + c) * 2u, A + (size_t)r * lda + k0 + c, 1);
        }
        {
            int r = tid >> 2, c = (tid & 3) * 8;
            cp16(so + (unsigned int)(RASZ + r * RBSTR + c) * 2u,
                 B + (size_t)(k0 + r) * ldb + c, 1);
        }
        asm volatile("cp.async.commit_group;\n" ::: "memory");
    };

    load_stage(0, 0);
    load_stage(1, 1);

    for (int kt = 0; kt < nk; ++kt) {
        asm volatile("cp.async.wait_group 1;\n" ::: "memory");
        __syncthreads();
        if (kt + 2 < nk) load_stage(kt + 2, (kt + 2) % 3);
        else asm volatile("cp.async.commit_group;\n" ::: "memory");

        const __half* Ab = sbufh + (kt % 3) * RSTG;
        const __half* Bb = Ab + RASZ;
        #pragma unroll
        for (int kk = 0; kk < 2; ++kk) {
            int k = kg * 32 + kk * 16;
            wmma::fragment<wmma::matrix_a, 16, 16, 16, __half, wmma::row_major> af0, af1;
            wmma::fragment<wmma::matrix_b, 16, 16, 16, __half, wmma::row_major> bf;
            wmma::load_matrix_sync(af0, Ab + (mh * 32) * RASTR + k, RASTR);
            wmma::load_matrix_sync(af1, Ab + (mh * 32 + 16) * RASTR + k, RASTR);
            wmma::load_matrix_sync(bf, Bb + k * RBSTR + nh * 16, RBSTR);
            wmma::mma_sync(acc0, af0, bf, acc0);
            wmma::mma_sync(acc1, af1, bf, acc1);
        }
    }
    asm volatile("cp.async.wait_group 0;\n" ::: "memory");
    __syncthreads();
}

__device__ __forceinline__ float sigm(float x) { return 1.f / (1.f + expf(-x)); }

__device__ __forceinline__ void comb_tile(
    const __half* __restrict__ h, const __half* __restrict__ Wcomb,
    float* __restrict__ comb, const float* __restrict__ bcat,
    int n0, __half* sbufh, float* sbuff)
{
    wmma::fragment<wmma::accumulator, 16, 16, 16, float> a0, a1;
    wmma::fill_fragment(a0, 0.f);
    wmma::fill_fragment(a1, 0.f);
    tile_gemm_64x64(h, 1536, Wcomb + n0, 5120, HH, sbufh, a0, a1);
    {
        const int wid = threadIdx.x >> 5;
        const int wm = wid & 1, wn = wid >> 1;
        wmma::store_matrix_sync(sbuff + (wm * 32) * 68 + wn * 16, a0, 68, wmma::mem_row_major);
        wmma::store_matrix_sync(sbuff + (wm * 32 + 16) * 68 + wn * 16, a1, 68, wmma::mem_row_major);
    }
    __syncthreads();
    const bool isAtt = (n0 < 1024);
    #pragma unroll
    for (int it = 0; it < 16; ++it) {
        int idx = threadIdx.x + it * 256;
        int r = idx >> 6, c = idx & 63;
        float v = sbuff[r * 68 + c];
        if (isAtt) v += bcat[n0 + c];
        comb[(size_t)r * 5120 + n0 + c] = v;
    }
    __syncthreads();
}

__global__ __launch_bounds__(256, 1)
void recur_kernel(const float* __restrict__ wfull,
                  const float* __restrict__ bfull,
                  float* __restrict__ alpha_out)
{
    extern __shared__ __half sbufh[];
    float* sbuff = (float*)sbufh;

    const int bi = blockIdx.x;
    const int tid = threadIdx.x;
    const int wid = tid >> 5, lane = tid & 31;

    float* S = g_scratch;
    const __half* att_ench = (const __half*)(S + OFF_ATT_ENC);
    const __half* ench     = (const __half*)(S + OFF_ENC_H);
    const __half* Wcomb    = (const __half*)(S + OFF_WCOMB);
    const __half* Wctx     = (const __half*)(S + OFF_WCTX);
    const float*  bcat     = S + OFF_BCAT;
    const float*  ebias    = S + OFF_EBIAS;
    __half* sxh            = (__half*)(S + OFF_SX);
    float* cbuf            = S + OFF_C;
    float* comb            = S + OFF_COMB;
    __half* hall           = (__half*)(S + OFF_HALL);

    const float bf0 = bfull[0];

    for (int t = 0; t < TT; ++t) {
        const int cur = t & 1, nxt = cur ^ 1;
        __half* sxc = sxh + cur * (64 * 1536);
        __half* sxn = sxh + nxt * (64 * 1536);
        const unsigned tgt16 = 16u * (unsigned)(t + 1);
        const unsigned tgt128 = 128u * (unsigned)(t + 1);

        if (bi >= 64) {
            int tile = bi - 64;
            if (tile < 16) {
                comb_tile(sxc + 512, Wcomb, comb, bcat, tile * 64, sbufh, sbuff);
                bar_arrive(&g_c_attdec);
                comb_tile(sxc + 512, Wcomb, comb, bcat, 1024 + (48 + tile) * 64, sbufh, sbuff);
            } else {
                comb_tile(sxc + 512, Wcomb, comb, bcat, 1024 + (tile - 16) * 64, sbufh, sbuff);
            }
            bar_arrive(&g_c_pre);
            bar_wait(&g_c_pre, tgt128);
        } else {
            bar_wait(&g_c_attdec, tgt16);
            const int b = bi;
            float* sa   = sbuff;
            float* sw   = sbuff + 512;
            float* se   = sbuff + 1024;
            float* sred = sbuff + 1248;
            float* sctx = sbuff + 1280;

            for (int i = tid; i < AA; i += 256) {
                sa[i] = comb[(size_t)b * 5120 + i];
                sw[i] = wfull[i];
            }
            __syncthreads();

            for (int p = wid; p < PP; p += 8) {
                const __half2* row = (const __half2*)(att_ench + (size_t)(b * PP + p) * AA);
                float acc = 0.f;
                #pragma unroll 4
                for (int a2 = lane; a2 < 256; a2 += 32) {
                    __half2 hv = row[a2];
                    float x0 = __low2float(hv)  + sa[a2 * 2];
                    float x1 = __high2float(hv) + sa[a2 * 2 + 1];
                    x0 = fmaxf(x0, 0.f); x1 = fmaxf(x1, 0.f);
                    acc += x0 * sw[a2 * 2] + x1 * sw[a2 * 2 + 1];
                }
                #pragma unroll
                for (int o = 16; o; o >>= 1) acc += __shfl_xor_sync(0xffffffffu, acc, o);
                if (lane == 0) se[p] = acc + bf0;
            }
            __syncthreads();

            float v = (tid < PP) ? se[tid] : -1e30f;
            float m = v;
            #pragma unroll
            for (int o = 16; o; o >>= 1) m = fmaxf(m, __shfl_xor_sync(0xffffffffu, m, o));
            if (lane == 0) sred[wid] = m;
            __syncthreads();
            if (wid == 0) {
                float mm = (lane < 8) ? sred[lane] : -1e30f;
                #pragma unroll
                for (int o = 16; o; o >>= 1) mm = fmaxf(mm, __shfl_xor_sync(0xffffffffu, mm, o));
                if (lane == 0) sred[0] = mm;
            }
            __syncthreads();
            float mx = sred[0];
            __syncthreads();

            float ex = (tid < PP) ? expf(v - mx) : 0.f;
            float s = ex;
            #pragma unroll
            for (int o = 16; o; o >>= 1) s += __shfl_xor_sync(0xffffffffu, s, o);
            if (lane == 0) sred[wid] = s;
            __syncthreads();
            if (wid == 0) {
                float ss = (lane < 8) ? sred[lane] : 0.f;
                #pragma unroll
                for (int o = 16; o; o >>= 1) ss += __shfl_xor_sync(0xffffffffu, ss, o);
                if (lane == 0) sred[0] = ss;
            }
            __syncthreads();
            float inv = 1.f / sred[0];

            if (tid < PP) {
                float al = ex * inv;
                se[tid] = al;
                alpha_out[((size_t)b * TT + t) * PP + tid] = al;
            }
            __syncthreads();

            {
                int grp = tid >> 7;
                int t2 = tid & 127;
                const __half2* base =
                    (const __half2*)(ench + ((size_t)(b * PP) + grp * 98) * ENC) + t2 * 2;
                const float* al = se + grp * 98;
                float4 acc4 = make_float4(0.f, 0.f, 0.f, 0.f);
                #pragma unroll 7
                for (int p = 0; p < 98; ++p) {
                    float a = al[p];
                    __half2 v01 = base[(size_t)p * 256];
                    __half2 v23 = base[(size_t)p * 256 + 1];
                    acc4.x += a * __low2float(v01);  acc4.y += a * __high2float(v01);
                    acc4.z += a * __low2float(v23);  acc4.w += a * __high2float(v23);
                }
                *(float4*)&sctx[grp * 512 + t2 * 4] = acc4;
            }
            __syncthreads();
            if (tid < 128) {
                float4 c0 = *(float4*)&sctx[tid * 4];
                float4 c1 = *(float4*)&sctx[512 + tid * 4];
                const float* fb = comb + (size_t)b * 5120 + 512 + tid * 4;
                __half2 h01 = __floats2half2_rn(sigm(fb[0]) * (c0.x + c1.x),
                                                sigm(fb[1]) * (c0.y + c1.y));
                __half2 h23 = __floats2half2_rn(sigm(fb[2]) * (c0.z + c1.z),
                                                sigm(fb[3]) * (c0.w + c1.w));
                *(__half2*)&sxc[b * 1536 + tid * 4]     = h01;
                *(__half2*)&sxc[b * 1536 + tid * 4 + 2] = h23;
            }
            bar_arrive(&g_c_pre);
            bar_wait(&g_c_pre, tgt128);
        }

        // ---- Phase C ----
        {
            wmma::fragment<wmma::accumulator, 16, 16, 16, float> a0, a1;
            wmma::fill_fragment(a0, 0.f);
            wmma::fill_fragment(a1, 0.f);
            const int n0 = bi * 32;
            tile_gemm_ws(sxc, 1536, Wctx + n0, 4096, ENC, sbufh, a0, a1);
            {
                const int kg = wid >> 2;
                const int nh = (wid >> 1) & 1;
                const int mh = wid & 1;
                float* Cs = sbuff + kg * 2304;
                wmma::store_matrix_sync(Cs + (mh * 32) * 36 + nh * 16, a0, 36, wmma::mem_row_major);
                wmma::store_matrix_sync(Cs + (mh * 32 + 16) * 36 + nh * 16, a1, 36, wmma::mem_row_major);
            }
            __syncthreads();

            #pragma unroll
            for (int i = 0; i < 2; ++i) {
                int p = tid + i * 256;
                int b = p >> 3, jj = p & 7;
                int j = bi * 8 + jj;
                float4 g0 = *(float4*)&sbuff[b * 36 + jj * 4];
                float4 g1 = *(float4*)&sbuff[2304 + b * 36 + jj * 4];
                float4 hp = *(const float4*)&comb[(size_t)b * 5120 + 1024 + n0 + jj * 4];
                float4 e = *(const float4*)&ebias[((size_t)t * BB + b) * 4096 + n0 + jj * 4];
                float gi = g0.x + g1.x + hp.x + e.x, gf = g0.y + g1.y + hp.y + e.y;
                float gg = g0.z + g1.z + hp.z + e.z, go = g0.w + g1.w + hp.w + e.w;
                float co = cbuf[b * 1024 + j];
                float cn = sigm(gf) * co + sigm(gi) * tanhf(gg);
                float h  = sigm(go) * tanhf(cn);
                __half hr = __float2half_rn(h);
                cbuf[b * 1024 + j] = cn;
                sxn[b * 1536 + 512 + j] = hr;
                hall[((size_t)t * BB + b) * 1024 + j] = hr;
            }
        }
        bar_arrive(&g_c_step);
        bar_wait(&g_c_step, tgt128);
    }
}

// ---------------- launch ----------------
extern "C" void kernel_launch(void* const* d_in, const int* in_sizes, int n_in,
                              void* d_out, int out_size)
{
    const float* enc       = (const float*)d_in[0];
    const int*   caps      = (const int*)  d_in[1];
    const float* W_enc_att = (const float*)d_in[3];
    const float* b_enc_att = (const float*)d_in[4];
    const float* W_dec_att = (const float*)d_in[5];
    const float* b_dec_att = (const float*)d_in[6];
    const float* W_full    = (const float*)d_in[7];
    const float* b_full    = (const float*)d_in[8];
    const float* emb       = (const float*)d_in[9];
    const float* W_ih      = (const float*)d_in[10];
    const float* b_ih      = (const float*)d_in[11];
    const float* W_hh      = (const float*)d_in[12];
    const float* b_hh      = (const float*)d_in[13];
    const float* W_init_h  = (const float*)d_in[14];
    const float* b_init_h  = (const float*)d_in[15];
    const float* W_init_c  = (const float*)d_in[16];
    const float* b_init_c  = (const float*)d_in[17];
    const float* W_fbeta   = (const float*)d_in[18];
    const float* b_fbeta   = (const float*)d_in[19];
    const float* W_fc      = (const float*)d_in[20];
    const float* b_fc      = (const float*)d_in[21];

    float* out = (float*)d_out;
    float* alpha_out = out + (size_t)BB * TT * VV;

    void* sp = nullptr;
    cudaGetSymbolAddress(&sp, g_scratch);
    float* S = (float*)sp;

    cudaFuncSetAttribute(gemm2<0>, cudaFuncAttributeMaxDynamicSharedMemorySize, G2_SMEM_BYTES);
    cudaFuncSetAttribute(gemm2<1>, cudaFuncAttributeMaxDynamicSharedMemorySize, G2_SMEM_BYTES);
    cudaFuncSetAttribute(gemm2<2>, cudaFuncAttributeMaxDynamicSharedMemorySize, G2_SMEM_BYTES);
    cudaFuncSetAttribute(gemm2<3>, cudaFuncAttributeMaxDynamicSharedMemorySize, G2_SMEM_BYTES);
    cudaFuncSetAttribute(recur_kernel, cudaFuncAttributeMaxDynamicSharedMemorySize, RSMEM_BYTES);

    prep_kernel<<<2048, 256>>>(W_dec_att, W_fbeta, b_dec_att, b_fbeta, W_ih, W_hh, b_ih, b_hh,
                               enc, emb, W_fc, W_enc_att, W_init_h, W_init_c,
                               b_init_h, b_init_c, caps);

    // [h0 | c0]
    gemm2<2><<<dim3(16, 1), 256, G2_SMEM_BYTES>>>(
        (const __half*)(S + OFF_MEAN), ENC, (const __half*)(S + OFF_W0), 2048,
        S, 0, S + OFF_B0, BB, 2048, ENC);

    // att_enc (fp16 output)
    gemm2<3><<<dim3(4, 98), 256, G2_SMEM_BYTES>>>(
        (const __half*)(S + OFF_ENC_H), ENC, (const __half*)(S + OFF_WEA_H), AA,
        S + OFF_ATT_ENC, AA, b_enc_att, BB * PP, AA, ENC);

    // ebias
    gemm2<0><<<dim3(32, 12), 256, G2_SMEM_BYTES>>>(
        (const __half*)(S + OFF_EMBG), EE, (const __half*)(S + OFF_WIH), 4096,
        S + OFF_EBIAS, 4096, S + OFF_BREC, TT * BB, 4096, EE);

    // persistent recurrence
    recur_kernel<<<NBLK, 256, RSMEM_BYTES>>>(W_full, b_full, alpha_out);

    // predictions
    gemm2<1><<<dim3(157, 12), 256, G2_SMEM_BYTES>>>(
        (const __half*)(S + OFF_HALL), HH, (const __half*)(S + OFF_WFC_H), VV,
        out, VV, b_fc, TT * BB, VV, HH);
}